// round 1
// baseline (speedup 1.0000x reference)
#include <cuda_runtime.h>
#include <cuda_bf16.h>
#include <cstdio>

// ---------------------------------------------------------------------------
// GraphConv stack: 14 layers of  y = X@W0^T + b0 ;  n = X@W1^T + b1 ;
// y += scatter_add(n over undirected edges) ; relu (except final layer).
// N=100000 nodes, D=128, E=300000 edges, 12 hidden layers, final 128->3.
// ---------------------------------------------------------------------------

#define D 128
#define MAXN 100352   // >= N, multiple of 128

// Scratch (device globals: no allocation allowed)
__device__ float g_x  [(size_t)MAXN * D];   // current activations (relu'd)
__device__ float g_y  [(size_t)MAXN * D];   // self-transform + aggregation
__device__ float g_n  [(size_t)MAXN * D];   // neighbor transform
__device__ float g_res[(size_t)MAXN * D];   // residual (after first layer)
__device__ float g_n3 [(size_t)MAXN * 3];   // final-layer neighbor transform

// ---------------------------------------------------------------------------
// Dual GEMM:  Out[r, c] = sum_k X[r,k] * W[c,k] + b[c]
// blockIdx.y == 0 -> (W0,b0)->Y ; blockIdx.y == 1 -> (W1,b1)->Nb
// Classic 128x128 tile, BK=16, 8x8 per thread, 256 threads.
// ---------------------------------------------------------------------------
__global__ __launch_bounds__(256) void gemm_dual(
    const float* __restrict__ X,
    const float* __restrict__ W0, const float* __restrict__ b0,
    const float* __restrict__ W1, const float* __restrict__ b1,
    float* __restrict__ Y, float* __restrict__ Nb, int nrows)
{
    const float* W    = (blockIdx.y == 0) ? W0 : W1;
    const float* bias = (blockIdx.y == 0) ? b0 : b1;
    float*       Out  = (blockIdx.y == 0) ? Y  : Nb;

    __shared__ float As[16][D + 4];   // [k][m]
    __shared__ float Bs[16][D + 4];   // [k][n]

    const int tid  = threadIdx.x;        // 0..255
    const int row0 = blockIdx.x * 128;
    const int tx   = tid & 15;           // 0..15
    const int ty   = tid >> 4;           // 0..15

    float acc[8][8];
#pragma unroll
    for (int i = 0; i < 8; i++)
#pragma unroll
        for (int j = 0; j < 8; j++) acc[i][j] = 0.f;

    for (int k0 = 0; k0 < D; k0 += 16) {
        // Load A tile: 128 rows x 16 k = 512 float4 -> 2 per thread
#pragma unroll
        for (int it = 0; it < 2; it++) {
            int idx = tid + it * 256;          // 0..511
            int m   = idx >> 2;                // 0..127
            int kq  = idx & 3;                 // float4 within 16 k's
            int r   = row0 + m;
            float4 v = make_float4(0.f, 0.f, 0.f, 0.f);
            if (r < nrows)
                v = *(const float4*)(X + (size_t)r * D + k0 + kq * 4);
            As[kq * 4 + 0][m] = v.x;
            As[kq * 4 + 1][m] = v.y;
            As[kq * 4 + 2][m] = v.z;
            As[kq * 4 + 3][m] = v.w;
        }
        // Load B tile: W[c, k] ; 128 cols x 16 k
#pragma unroll
        for (int it = 0; it < 2; it++) {
            int idx = tid + it * 256;
            int c   = idx >> 2;
            int kq  = idx & 3;
            float4 v = *(const float4*)(W + (size_t)c * D + k0 + kq * 4);
            Bs[kq * 4 + 0][c] = v.x;
            Bs[kq * 4 + 1][c] = v.y;
            Bs[kq * 4 + 2][c] = v.z;
            Bs[kq * 4 + 3][c] = v.w;
        }
        __syncthreads();

#pragma unroll
        for (int kk = 0; kk < 16; kk++) {
            float a[8], b[8];
#pragma unroll
            for (int i = 0; i < 8; i++) a[i] = As[kk][ty * 8 + i];
#pragma unroll
            for (int j = 0; j < 8; j++) b[j] = Bs[kk][tx * 8 + j];
#pragma unroll
            for (int i = 0; i < 8; i++)
#pragma unroll
                for (int j = 0; j < 8; j++)
                    acc[i][j] = fmaf(a[i], b[j], acc[i][j]);
        }
        __syncthreads();
    }

#pragma unroll
    for (int i = 0; i < 8; i++) {
        int r = row0 + ty * 8 + i;
        if (r >= nrows) continue;
#pragma unroll
        for (int j = 0; j < 8; j++) {
            int c = tx * 8 + j;
            Out[(size_t)r * D + c] = acc[i][j] + bias[c];
        }
    }
}

// ---------------------------------------------------------------------------
// Undirected scatter: for each edge (i,j): Y[i,:] += Nb[j,:]; Y[j,:] += Nb[i,:]
// One warp per edge; each lane handles one float4 chunk (128/4 = 32 lanes).
// ---------------------------------------------------------------------------
__global__ __launch_bounds__(256) void scatter_add(
    const int* __restrict__ edges, const float* __restrict__ Nb,
    float* __restrict__ Y, int E)
{
    int g    = blockIdx.x * blockDim.x + threadIdx.x;
    int e    = g >> 5;
    int lane = g & 31;
    if (e >= E) return;
    int i = edges[2 * e];
    int j = edges[2 * e + 1];

    float4 vj = *(const float4*)(Nb + (size_t)j * D + lane * 4);
    float4 vi = *(const float4*)(Nb + (size_t)i * D + lane * 4);
    float* yi = Y + (size_t)i * D + lane * 4;
    float* yj = Y + (size_t)j * D + lane * 4;

    atomicAdd(yi + 0, vj.x); atomicAdd(yi + 1, vj.y);
    atomicAdd(yi + 2, vj.z); atomicAdd(yi + 3, vj.w);
    atomicAdd(yj + 0, vi.x); atomicAdd(yj + 1, vi.y);
    atomicAdd(yj + 2, vi.z); atomicAdd(yj + 3, vi.w);
}

// ---------------------------------------------------------------------------
// ReLU epilogue: X = relu(Y); optional residual / auxiliary copies.
// ---------------------------------------------------------------------------
__global__ __launch_bounds__(256) void relu_store(
    const float* __restrict__ Y, float* __restrict__ X,
    float* __restrict__ res, float* __restrict__ aux, int nquads)
{
    int idx = blockIdx.x * blockDim.x + threadIdx.x;
    if (idx >= nquads) return;
    float4 v = ((const float4*)Y)[idx];
    v.x = fmaxf(v.x, 0.f); v.y = fmaxf(v.y, 0.f);
    v.z = fmaxf(v.z, 0.f); v.w = fmaxf(v.w, 0.f);
    ((float4*)X)[idx] = v;
    if (res) ((float4*)res)[idx] = v;
    if (aux) ((float4*)aux)[idx] = v;
}

// ---------------------------------------------------------------------------
// Final layer (128 -> 3): z = res + x;  vert = z@W0^T + b0; n3 = z@W1^T + b1
// One thread per node.
// ---------------------------------------------------------------------------
__global__ __launch_bounds__(256) void final_gconv(
    const float* __restrict__ res, const float* __restrict__ x,
    const float* __restrict__ W0, const float* __restrict__ b0,
    const float* __restrict__ W1, const float* __restrict__ b1,
    float* __restrict__ vert, float* __restrict__ n3, int nrows)
{
    __shared__ float sW0[3 * D], sW1[3 * D], sb0[3], sb1[3];
    for (int t = threadIdx.x; t < 3 * D; t += blockDim.x) {
        sW0[t] = W0[t];
        sW1[t] = W1[t];
    }
    if (threadIdx.x < 3) {
        sb0[threadIdx.x] = b0[threadIdx.x];
        sb1[threadIdx.x] = b1[threadIdx.x];
    }
    __syncthreads();

    int node = blockIdx.x * blockDim.x + threadIdx.x;
    if (node >= nrows) return;

    const float4* r4 = (const float4*)(res + (size_t)node * D);
    const float4* x4 = (const float4*)(x   + (size_t)node * D);

    float accY[3] = {sb0[0], sb0[1], sb0[2]};
    float accN[3] = {sb1[0], sb1[1], sb1[2]};

#pragma unroll 8
    for (int q = 0; q < D / 4; q++) {
        float4 a = r4[q], b = x4[q];
        float z0 = a.x + b.x, z1 = a.y + b.y, z2 = a.z + b.z, z3 = a.w + b.w;
        int k = q * 4;
#pragma unroll
        for (int o = 0; o < 3; o++) {
            accY[o] = fmaf(z0, sW0[o * D + k + 0], accY[o]);
            accY[o] = fmaf(z1, sW0[o * D + k + 1], accY[o]);
            accY[o] = fmaf(z2, sW0[o * D + k + 2], accY[o]);
            accY[o] = fmaf(z3, sW0[o * D + k + 3], accY[o]);
            accN[o] = fmaf(z0, sW1[o * D + k + 0], accN[o]);
            accN[o] = fmaf(z1, sW1[o * D + k + 1], accN[o]);
            accN[o] = fmaf(z2, sW1[o * D + k + 2], accN[o]);
            accN[o] = fmaf(z3, sW1[o * D + k + 3], accN[o]);
        }
    }
#pragma unroll
    for (int o = 0; o < 3; o++) {
        vert[(size_t)node * 3 + o] = accY[o];
        n3  [(size_t)node * 3 + o] = accN[o];
    }
}

__global__ __launch_bounds__(256) void scatter3(
    const int* __restrict__ edges, const float* __restrict__ n3,
    float* __restrict__ vert, int E)
{
    int e = blockIdx.x * blockDim.x + threadIdx.x;
    if (e >= E) return;
    int i = edges[2 * e];
    int j = edges[2 * e + 1];
#pragma unroll
    for (int o = 0; o < 3; o++) {
        atomicAdd(&vert[(size_t)i * 3 + o], n3[(size_t)j * 3 + o]);
        atomicAdd(&vert[(size_t)j * 3 + o], n3[(size_t)i * 3 + o]);
    }
}

// ---------------------------------------------------------------------------
extern "C" void kernel_launch(void* const* d_in, const int* in_sizes, int n_in,
                              void* d_out, int out_size)
{
    const float* features = (const float*)d_in[0];
    const int*   edges    = (const int*)  d_in[1];
    const float* W0_1 = (const float*)d_in[2];
    const float* b0_1 = (const float*)d_in[3];
    const float* W1_1 = (const float*)d_in[4];
    const float* b1_1 = (const float*)d_in[5];
    const float* W0_h = (const float*)d_in[6];
    const float* b0_h = (const float*)d_in[7];
    const float* W1_h = (const float*)d_in[8];
    const float* b1_h = (const float*)d_in[9];
    const float* W0_l = (const float*)d_in[10];
    const float* b0_l = (const float*)d_in[11];
    const float* W1_l = (const float*)d_in[12];
    const float* b1_l = (const float*)d_in[13];

    const int Nn = in_sizes[0] / D;
    const int E  = in_sizes[1] / 2;
    const int Lh = in_sizes[6] / (D * D);

    float* out  = (float*)d_out;
    float* vert = out;                       // [N, 3]
    float* aux  = out + (size_t)Nn * 3;      // [N, 128]

    // Resolve scratch symbol addresses (host-side, not captured, no alloc).
    float *p_x, *p_y, *p_n, *p_res, *p_n3;
    cudaGetSymbolAddress((void**)&p_x,   g_x);
    cudaGetSymbolAddress((void**)&p_y,   g_y);
    cudaGetSymbolAddress((void**)&p_n,   g_n);
    cudaGetSymbolAddress((void**)&p_res, g_res);
    cudaGetSymbolAddress((void**)&p_n3,  g_n3);

    const dim3 gemm_grid((Nn + 127) / 128, 2);
    const int  scat_blocks  = (E * 32 + 255) / 256;
    const int  nquads       = Nn * D / 4;
    const int  relu_blocks  = (nquads + 255) / 256;
    const int  node_blocks  = (Nn + 255) / 256;
    const int  edge_blocks  = (E + 255) / 256;

    // ---- Layer 1: features -> x (relu), also residual -------------------
    gemm_dual<<<gemm_grid, 256>>>(features, W0_1, b0_1, W1_1, b1_1, p_y, p_n, Nn);
    scatter_add<<<scat_blocks, 256>>>(edges, p_n, p_y, E);
    relu_store<<<relu_blocks, 256>>>(p_y, p_x, p_res, nullptr, nquads);

    // ---- 12 hidden layers ------------------------------------------------
    for (int l = 0; l < Lh; l++) {
        const float* W0 = W0_h + (size_t)l * D * D;
        const float* b0 = b0_h + (size_t)l * D;
        const float* W1 = W1_h + (size_t)l * D * D;
        const float* b1 = b1_h + (size_t)l * D;
        gemm_dual<<<gemm_grid, 256>>>(p_x, W0, b0, W1, b1, p_y, p_n, Nn);
        scatter_add<<<scat_blocks, 256>>>(edges, p_n, p_y, E);
        float* aux_ptr = (l == Lh - 1) ? aux : nullptr;   // auxiliary output
        relu_store<<<relu_blocks, 256>>>(p_y, p_x, nullptr, aux_ptr, nquads);
    }

    // ---- Final layer: (res + x) -> vertices [N,3] ------------------------
    final_gconv<<<node_blocks, 256>>>(p_res, p_x, W0_l, b0_l, W1_l, b1_l,
                                      vert, p_n3, Nn);
    scatter3<<<edge_blocks, 256>>>(edges, p_n3, vert, E);
}